// round 12
// baseline (speedup 1.0000x reference)
#include <cuda_runtime.h>
#include <cuda_fp16.h>
#include <cstdint>
#include <math.h>

#define BATCH 4
#define SEQ 2048
#define CH 768
#define NHEADS 12
#define HD 64
#define MTOT (BATCH * SEQ)   // 8192
#define C3 (3 * CH)          // 2304

// Scratch (allocation-free contract) — all fp16
__device__ __half g_x[(size_t)MTOT * CH];
__device__ __half g_qkv[(size_t)MTOT * C3];
__device__ __half g_att[(size_t)MTOT * CH];
__device__ __half g_wqkvT[(size_t)C3 * CH];
__device__ __half g_wprojT[(size_t)CH * CH];

__device__ __forceinline__ uint32_t smem_u32(const void* p) {
    uint32_t a;
    asm("{ .reg .u64 t; cvta.to.shared.u64 t, %1; cvt.u32.u64 %0, t; }"
        : "=r"(a) : "l"(p));
    return a;
}
#define CP16(dst, src) \
    asm volatile("cp.async.cg.shared.global [%0], [%1], 16;" \
                 :: "r"(dst), "l"(src) : "memory")
#define CP_COMMIT() asm volatile("cp.async.commit_group;" ::: "memory")
#define CP_WAIT(n)  asm volatile("cp.async.wait_group %0;" :: "n"(n) : "memory")

// m16n8k16 fp16 mma, fp32 accumulate in-place.
__device__ __forceinline__ void mma16(float* c, const unsigned* a,
                                      unsigned b0, unsigned b1) {
    asm volatile(
        "mma.sync.aligned.m16n8k16.row.col.f32.f16.f16.f32 "
        "{%0,%1,%2,%3}, {%4,%5,%6,%7}, {%8,%9}, {%0,%1,%2,%3};"
        : "+f"(c[0]), "+f"(c[1]), "+f"(c[2]), "+f"(c[3])
        : "r"(a[0]), "r"(a[1]), "r"(a[2]), "r"(a[3]), "r"(b0), "r"(b1));
}
__device__ __forceinline__ void ldsm4(unsigned& r0, unsigned& r1,
                                      unsigned& r2, unsigned& r3,
                                      uint32_t addr) {
    asm volatile("ldmatrix.sync.aligned.m8n8.x4.shared.b16 {%0,%1,%2,%3}, [%4];"
                 : "=r"(r0), "=r"(r1), "=r"(r2), "=r"(r3) : "r"(addr));
}
__device__ __forceinline__ void ldsm4t(unsigned& r0, unsigned& r1,
                                       unsigned& r2, unsigned& r3,
                                       uint32_t addr) {
    asm volatile("ldmatrix.sync.aligned.m8n8.x4.trans.shared.b16 {%0,%1,%2,%3}, [%4];"
                 : "=r"(r0), "=r"(r1), "=r"(r2), "=r"(r3) : "r"(addr));
}
__device__ __forceinline__ unsigned packh2(float a, float b) {
    __half2 h = __floats2half2_rn(a, b);
    return *(unsigned*)&h;
}

// ---------------------------------------------------------------------------
// Prepass: round x to fp16
// ---------------------------------------------------------------------------
__global__ __launch_bounds__(256) void round_kernel(
    const float* __restrict__ in, __half* __restrict__ outp)
{
    const int idx = blockIdx.x * 256 + threadIdx.x;
    float4 v = ((const float4*)in)[idx];
    __half2 h0 = __floats2half2_rn(v.x, v.y);
    __half2 h1 = __floats2half2_rn(v.z, v.w);
    uint2 o = { *(unsigned*)&h0, *(unsigned*)&h1 };
    ((uint2*)outp)[idx] = o;
}

// ---------------------------------------------------------------------------
// Weight transpose to fp16: Wt[n][k] = half(W[k][n])
// ---------------------------------------------------------------------------
__global__ __launch_bounds__(256) void transpose_kernel(
    const float* __restrict__ W, __half* __restrict__ Wt, int R, int Cc)
{
    __shared__ float t[32][33];
    const int bx = blockIdx.x * 32, by = blockIdx.y * 32;
    const int x = threadIdx.x & 31, y4 = (threadIdx.x >> 5) * 4;
    #pragma unroll
    for (int j = 0; j < 4; j++)
        t[y4 + j][x] = W[(long)(by + y4 + j) * Cc + bx + x];
    __syncthreads();
    #pragma unroll
    for (int j = 0; j < 4; j++)
        Wt[(long)(bx + y4 + j) * R + by + x] = __float2half_rn(t[x][y4 + j]);
}

// ---------------------------------------------------------------------------
// fp16 mma.sync GEMM + bias: C[M,N] = A[M,K] @ Bt[N,K]^T + bias
// 128x128 CTA tile, BK=64, 256 threads (8 warps 4x2, warp 32x64).
// 3-STAGE cp.async ring, ONE __syncthreads per k-iter, 2 CTAs/SM.
// ---------------------------------------------------------------------------
#define HS 72
#define HTILE (128 * HS)   // halves per operand tile

template <bool HALF_OUT>
__global__ __launch_bounds__(256, 2) void gemm_fp16(
    const __half* __restrict__ A, const __half* __restrict__ Bt,
    const float* __restrict__ bias, void* __restrict__ Cout,
    int M, int N, int K)
{
    extern __shared__ __half hsm[];   // 3 stages x (A | B)
    const int tid = threadIdx.x;
    const int lane = tid & 31, wid = tid >> 5;
    const int g = lane >> 2, tq = lane & 3;
    const int wm = (wid & 3) * 32, wn = (wid >> 2) * 64;
    const int bm = blockIdx.y * 128, bn = blockIdx.x * 128;
    const int sr = tid >> 3, sc8 = (tid & 7) * 8;

    const uint32_t sbase = smem_u32(hsm);
    const uint32_t a_base0 = sbase +
        ((wm + (lane & 15)) * HS + (lane >> 4) * 8) * 2;
    const uint32_t b_base0 = sbase + HTILE * 2 +
        ((wn + (lane & 7) + (lane >> 4) * 8) * HS + ((lane >> 3) & 1) * 8) * 2;

    float acc[2][8][4];
    #pragma unroll
    for (int mt = 0; mt < 2; mt++)
        #pragma unroll
        for (int nt = 0; nt < 8; nt++)
            #pragma unroll
            for (int j = 0; j < 4; j++) acc[mt][nt][j] = 0.f;

    const int NK = K / 64;
    auto issue = [&](int kt, int st) {
        __half* As = hsm + st * 2 * HTILE;
        __half* Bs = As + HTILE;
        const int k0 = kt * 64;
        #pragma unroll
        for (int i = 0; i < 4; i++) {
            int r = sr + 32 * i;
            CP16(smem_u32(As + r * HS + sc8),
                 A + (long)(bm + r) * K + k0 + sc8);
            CP16(smem_u32(Bs + r * HS + sc8),
                 Bt + (long)(bn + r) * K + k0 + sc8);
        }
        CP_COMMIT();
    };

    issue(0, 0);
    issue(1, 1);
    int st = 0;
    for (int kt = 0; kt < NK; kt++) {
        CP_WAIT(1);          // tile kt landed (kt+1 may remain in flight)
        __syncthreads();     // all warps finished compute(kt-1) -> stage free
        if (kt + 2 < NK) issue(kt + 2, (st + 2) % 3);

        const uint32_t a_buf = a_base0 + st * 2 * HTILE * 2;
        const uint32_t b_buf = b_base0 + st * 2 * HTILE * 2;
        #pragma unroll
        for (int ks = 0; ks < 4; ks++) {
            unsigned af[2][4];
            ldsm4(af[0][0], af[0][1], af[0][2], af[0][3], a_buf + ks * 32);
            ldsm4(af[1][0], af[1][1], af[1][2], af[1][3],
                  a_buf + 16 * HS * 2 + ks * 32);
            #pragma unroll
            for (int p = 0; p < 4; p++) {
                unsigned b0, b1, c0, c1;
                ldsm4(b0, b1, c0, c1, b_buf + p * 16 * HS * 2 + ks * 32);
                mma16(acc[0][2 * p],     af[0], b0, b1);
                mma16(acc[1][2 * p],     af[1], b0, b1);
                mma16(acc[0][2 * p + 1], af[0], c0, c1);
                mma16(acc[1][2 * p + 1], af[1], c0, c1);
            }
        }
        st = (st + 1) % 3;
    }

    #pragma unroll
    for (int mt = 0; mt < 2; mt++) {
        const long r0 = bm + wm + mt * 16 + g;
        #pragma unroll
        for (int nt = 0; nt < 8; nt++) {
            const int col = bn + wn + nt * 8 + 2 * tq;
            const float bz0 = bias[col], bz1 = bias[col + 1];
            if (HALF_OUT) {
                __half* C = (__half*)Cout;
                __half2 v0 = __floats2half2_rn(acc[mt][nt][0] + bz0,
                                               acc[mt][nt][1] + bz1);
                __half2 v1 = __floats2half2_rn(acc[mt][nt][2] + bz0,
                                               acc[mt][nt][3] + bz1);
                *(__half2*)(C + r0 * N + col)       = v0;
                *(__half2*)(C + (r0 + 8) * N + col) = v1;
            } else {
                float* C = (float*)Cout;
                float2 v0 = { acc[mt][nt][0] + bz0, acc[mt][nt][1] + bz1 };
                float2 v1 = { acc[mt][nt][2] + bz0, acc[mt][nt][3] + bz1 };
                *(float2*)(C + r0 * N + col)       = v0;
                *(float2*)(C + (r0 + 8) * N + col) = v1;
            }
        }
    }
}

// ---------------------------------------------------------------------------
// Flash attention fp16: Br=128, Bc=64, 128 threads (4 warps), 3 CTAs/SM.
// 3-STAGE KV cp.async ring; P kept in registers (S C-frag -> PV A-frag);
// l row-sum kept as per-thread partial (quad-reduced once in epilogue).
// Smem (halves, stride 72): Q 128 | 3 x (K 64 + V 64) = 73728 B.
// ---------------------------------------------------------------------------
#define QS_OFF 0
#define KV_OFF (128 * HS)
#define KVSTG (2 * 64 * HS)                      // halves per stage (K+V)
#define FL_HALVES (128 * HS + 3 * KVSTG)         // 36864 halves = 73728 B
#define NTILES (SEQ / 64)                        // 32

__global__ __launch_bounds__(128, 3) void flash_fp16()
{
    extern __shared__ __half fsm[];
    __half* Qs = fsm + QS_OFF;

    const int tid = threadIdx.x;
    const int lane = tid & 31, w = tid >> 5;
    const int g = lane >> 2, tq = lane & 3;
    const int b = blockIdx.y / NHEADS, h = blockIdx.y % NHEADS;
    const int q0 = blockIdx.x * 128;
    const long rowbase = (long)b * SEQ;
    const float kscale = 0.125f * 1.44269504089f;   // 1/sqrt(d) * log2(e)

    const uint32_t q_base = smem_u32(Qs) +
        ((w * 32 + (lane & 15)) * HS + (lane >> 4) * 8) * 2;
    const uint32_t kv_base = smem_u32(fsm + KV_OFF);
    const uint32_t k_frag = kv_base +
        (((lane & 7) + (lane >> 4) * 8) * HS + ((lane >> 3) & 1) * 8) * 2;
    const uint32_t v_frag = kv_base + 64 * HS * 2 +
        (((lane & 7) + ((lane >> 3) & 1) * 8) * HS + (lane >> 4) * 8) * 2;

    // Stage Q: 128 rows x 8 chunks of 8 halves (uint4), scale via f32.
    #pragma unroll
    for (int i = 0; i < 8; i++) {
        int idx = tid + 128 * i;
        int r = idx >> 3, c8 = (idx & 7) * 8;
        uint4 v = *(const uint4*)&g_qkv[(rowbase + q0 + r) * C3 + h * HD + c8];
        __half2* hp = (__half2*)&v;
        #pragma unroll
        for (int j = 0; j < 4; j++) {
            float2 f = __half22float2(hp[j]);
            hp[j] = __floats2half2_rn(f.x * kscale, f.y * kscale);
        }
        *(uint4*)(Qs + r * HS + c8) = v;
    }

    // KV staging: tile t into stage stg (K then V inside one stage)
    auto issue_kv = [&](int t, int stg) {
        __half* Kd = fsm + KV_OFF + stg * KVSTG;
        __half* Vd = Kd + 64 * HS;
        const int k0 = t * 64;
        #pragma unroll
        for (int i = 0; i < 4; i++) {
            int idx = tid + 128 * i;
            int r = idx >> 3, c8 = (idx & 7) * 8;
            long gb = (rowbase + k0 + r) * C3 + h * HD + c8;
            CP16(smem_u32(Kd + r * HS + c8), &g_qkv[gb + CH]);
            CP16(smem_u32(Vd + r * HS + c8), &g_qkv[gb + 2 * CH]);
        }
        CP_COMMIT();
    };

    float o[2][8][4];
    float m_i[2][2], l_p[2][2];   // l_p: per-thread PARTIAL row sums
    #pragma unroll
    for (int mt = 0; mt < 2; mt++) {
        m_i[mt][0] = m_i[mt][1] = -1e30f;
        l_p[mt][0] = l_p[mt][1] = 0.f;
        #pragma unroll
        for (int nt = 0; nt < 8; nt++)
            #pragma unroll
            for (int j = 0; j < 4; j++) o[mt][nt][j] = 0.f;
    }

    issue_kv(0, 0);
    issue_kv(1, 1);
    int stg = 0;
    for (int t = 0; t < NTILES; t++) {
        CP_WAIT(1);          // KV(t) landed
        __syncthreads();     // all warps done with stage (t-1) -> stage free
        if (t + 2 < NTILES) issue_kv(t + 2, (stg + 2) % 3);

        const uint32_t k_buf = k_frag + stg * KVSTG * 2;
        const uint32_t v_buf = v_frag + stg * KVSTG * 2;

        // S = Q @ K^T  (4 x k16 over d=64)
        float s[2][8][4];
        #pragma unroll
        for (int mt = 0; mt < 2; mt++)
            #pragma unroll
            for (int nt = 0; nt < 8; nt++)
                #pragma unroll
                for (int j = 0; j < 4; j++) s[mt][nt][j] = 0.f;
        #pragma unroll
        for (int ks = 0; ks < 4; ks++) {
            unsigned af[2][4];
            ldsm4(af[0][0], af[0][1], af[0][2], af[0][3], q_base + ks * 32);
            ldsm4(af[1][0], af[1][1], af[1][2], af[1][3],
                  q_base + 16 * HS * 2 + ks * 32);
            #pragma unroll
            for (int p = 0; p < 4; p++) {
                unsigned b0, b1, c0, c1;
                ldsm4(b0, b1, c0, c1, k_buf + p * 16 * HS * 2 + ks * 32);
                mma16(s[0][2 * p],     af[0], b0, b1);
                mma16(s[1][2 * p],     af[1], b0, b1);
                mma16(s[0][2 * p + 1], af[0], c0, c1);
                mma16(s[1][2 * p + 1], af[1], c0, c1);
            }
        }

        // Online softmax (base-2); pack exp2 straight into PV A-frags.
        // Row max IS quad-reduced (needed for exp range); row sum is NOT —
        // kept as per-thread partial, reduced once in the epilogue.
        unsigned pa[2][4][4];   // [mt][k16-step][frag]
        #pragma unroll
        for (int mt = 0; mt < 2; mt++) {
            float mx0 = -1e30f, mx1 = -1e30f;
            #pragma unroll
            for (int nt = 0; nt < 8; nt++) {
                mx0 = fmaxf(mx0, fmaxf(s[mt][nt][0], s[mt][nt][1]));
                mx1 = fmaxf(mx1, fmaxf(s[mt][nt][2], s[mt][nt][3]));
            }
            mx0 = fmaxf(mx0, __shfl_xor_sync(0xffffffffu, mx0, 1));
            mx0 = fmaxf(mx0, __shfl_xor_sync(0xffffffffu, mx0, 2));
            mx1 = fmaxf(mx1, __shfl_xor_sync(0xffffffffu, mx1, 1));
            mx1 = fmaxf(mx1, __shfl_xor_sync(0xffffffffu, mx1, 2));
            const float mn0 = fmaxf(m_i[mt][0], mx0), mn1 = fmaxf(m_i[mt][1], mx1);
            const float cr0 = exp2f(m_i[mt][0] - mn0), cr1 = exp2f(m_i[mt][1] - mn1);
            float rs0 = 0.f, rs1 = 0.f;
            #pragma unroll
            for (int j = 0; j < 4; j++) {      // k16 step = nt pair (2j, 2j+1)
                float e00 = exp2f(s[mt][2*j][0] - mn0);
                float e01 = exp2f(s[mt][2*j][1] - mn0);
                float e02 = exp2f(s[mt][2*j][2] - mn1);
                float e03 = exp2f(s[mt][2*j][3] - mn1);
                float e10 = exp2f(s[mt][2*j+1][0] - mn0);
                float e11 = exp2f(s[mt][2*j+1][1] - mn0);
                float e12 = exp2f(s[mt][2*j+1][2] - mn1);
                float e13 = exp2f(s[mt][2*j+1][3] - mn1);
                rs0 += (e00 + e01) + (e10 + e11);
                rs1 += (e02 + e03) + (e12 + e13);
                pa[mt][j][0] = packh2(e00, e01);
                pa[mt][j][1] = packh2(e02, e03);
                pa[mt][j][2] = packh2(e10, e11);
                pa[mt][j][3] = packh2(e12, e13);
            }
            l_p[mt][0] = l_p[mt][0] * cr0 + rs0;   // partial (quad-unreduced)
            l_p[mt][1] = l_p[mt][1] * cr1 + rs1;
            m_i[mt][0] = mn0; m_i[mt][1] = mn1;
            #pragma unroll
            for (int nt = 0; nt < 8; nt++) {
                o[mt][nt][0] *= cr0; o[mt][nt][1] *= cr0;
                o[mt][nt][2] *= cr1; o[mt][nt][3] *= cr1;
            }
        }

        // O += P @ V  (P from registers; V via ldmatrix.trans)
        #pragma unroll
        for (int ks = 0; ks < 4; ks++) {
            #pragma unroll
            for (int p = 0; p < 4; p++) {
                unsigned b0, b1, c0, c1;
                ldsm4t(b0, b1, c0, c1,
                       v_buf + ks * 16 * HS * 2 + p * 16 * 2);
                mma16(o[0][2 * p],     pa[0][ks], b0, b1);
                mma16(o[1][2 * p],     pa[1][ks], b0, b1);
                mma16(o[0][2 * p + 1], pa[0][ks], c0, c1);
                mma16(o[1][2 * p + 1], pa[1][ks], c0, c1);
            }
        }
        stg = (stg + 1) % 3;
    }

    // Epilogue: quad-reduce l partials (corr factors were quad-uniform),
    // normalize, store fp16 (feeds proj GEMM).
    #pragma unroll
    for (int mt = 0; mt < 2; mt++) {
        float l0 = l_p[mt][0], l1 = l_p[mt][1];
        l0 += __shfl_xor_sync(0xffffffffu, l0, 1);
        l0 += __shfl_xor_sync(0xffffffffu, l0, 2);
        l1 += __shfl_xor_sync(0xffffffffu, l1, 1);
        l1 += __shfl_xor_sync(0xffffffffu, l1, 2);
        const float inv0 = 1.f / l0, inv1 = 1.f / l1;
        const long r0 = rowbase + q0 + w * 32 + mt * 16 + g;
        #pragma unroll
        for (int nt = 0; nt < 8; nt++) {
            const int col = h * HD + nt * 8 + 2 * tq;
            *(__half2*)(g_att + r0 * CH + col) =
                __floats2half2_rn(o[mt][nt][0] * inv0, o[mt][nt][1] * inv0);
            *(__half2*)(g_att + (r0 + 8) * CH + col) =
                __floats2half2_rn(o[mt][nt][2] * inv1, o[mt][nt][3] * inv1);
        }
    }
}

// ---------------------------------------------------------------------------
extern "C" void kernel_launch(void* const* d_in, const int* in_sizes, int n_in,
                              void* d_out, int out_size)
{
    const float* x     = (const float*)d_in[0];
    const float* Wqkv  = (const float*)d_in[1];
    const float* bqkv  = (const float*)d_in[2];
    const float* Wproj = (const float*)d_in[3];
    const float* bproj = (const float*)d_in[4];
    float* out = (float*)d_out;

    __half *xr, *qkv_ptr, *att_ptr, *wqkvT, *wprojT;
    cudaGetSymbolAddress((void**)&xr, g_x);
    cudaGetSymbolAddress((void**)&qkv_ptr, g_qkv);
    cudaGetSymbolAddress((void**)&att_ptr, g_att);
    cudaGetSymbolAddress((void**)&wqkvT, g_wqkvT);
    cudaGetSymbolAddress((void**)&wprojT, g_wprojT);

    static int smem_set = 0;
    const int gemm_smem  = 6 * HTILE * sizeof(__half);    // 110592 B (3 stages)
    const int flash_smem = FL_HALVES * sizeof(__half);    // 73728 B
    if (!smem_set) {
        cudaFuncSetAttribute(gemm_fp16<true>,
            cudaFuncAttributeMaxDynamicSharedMemorySize, gemm_smem);
        cudaFuncSetAttribute(gemm_fp16<false>,
            cudaFuncAttributeMaxDynamicSharedMemorySize, gemm_smem);
        cudaFuncSetAttribute(flash_fp16,
            cudaFuncAttributeMaxDynamicSharedMemorySize, flash_smem);
        smem_set = 1;
    }

    // Pre-round x to fp16; transpose weights to fp16
    round_kernel<<<(MTOT * CH) / 1024, 256>>>(x, xr);
    transpose_kernel<<<dim3(C3 / 32, CH / 32), 256>>>(Wqkv, wqkvT, CH, C3);
    transpose_kernel<<<dim3(CH / 32, CH / 32), 256>>>(Wproj, wprojT, CH, CH);

    // QKV projection (fp16 output)
    gemm_fp16<true><<<dim3(C3 / 128, MTOT / 128), 256, gemm_smem>>>(
        xr, wqkvT, bqkv, qkv_ptr, MTOT, C3, CH);
    // Flash attention (3 CTAs/SM, 3-stage KV, P in registers)
    flash_fp16<<<dim3(SEQ / 128, BATCH * NHEADS), 128, flash_smem>>>();
    // Output projection (fp32 output)
    gemm_fp16<false><<<dim3(CH / 128, MTOT / 128), 256, gemm_smem>>>(
        att_ptr, wprojT, bproj, out, MTOT, CH, CH);
}

// round 13
// speedup vs baseline: 1.0572x; 1.0572x over previous
#include <cuda_runtime.h>
#include <cuda_fp16.h>
#include <cstdint>
#include <math.h>

#define BATCH 4
#define SEQ 2048
#define CH 768
#define NHEADS 12
#define HD 64
#define MTOT (BATCH * SEQ)   // 8192
#define C3 (3 * CH)          // 2304

// Scratch (allocation-free contract) — all fp16
__device__ __half g_x[(size_t)MTOT * CH];
__device__ __half g_qkv[(size_t)MTOT * C3];
__device__ __half g_att[(size_t)MTOT * CH];
__device__ __half g_wqkvT[(size_t)C3 * CH];
__device__ __half g_wprojT[(size_t)CH * CH];

__device__ __forceinline__ uint32_t smem_u32(const void* p) {
    uint32_t a;
    asm("{ .reg .u64 t; cvta.to.shared.u64 t, %1; cvt.u32.u64 %0, t; }"
        : "=r"(a) : "l"(p));
    return a;
}
#define CP16(dst, src) \
    asm volatile("cp.async.cg.shared.global [%0], [%1], 16;" \
                 :: "r"(dst), "l"(src) : "memory")
#define CP_COMMIT() asm volatile("cp.async.commit_group;" ::: "memory")
#define CP_WAIT(n)  asm volatile("cp.async.wait_group %0;" :: "n"(n) : "memory")

// m16n8k16 fp16 mma, fp32 accumulate in-place.
__device__ __forceinline__ void mma16(float* c, const unsigned* a,
                                      unsigned b0, unsigned b1) {
    asm volatile(
        "mma.sync.aligned.m16n8k16.row.col.f32.f16.f16.f32 "
        "{%0,%1,%2,%3}, {%4,%5,%6,%7}, {%8,%9}, {%0,%1,%2,%3};"
        : "+f"(c[0]), "+f"(c[1]), "+f"(c[2]), "+f"(c[3])
        : "r"(a[0]), "r"(a[1]), "r"(a[2]), "r"(a[3]), "r"(b0), "r"(b1));
}
__device__ __forceinline__ void ldsm4(unsigned& r0, unsigned& r1,
                                      unsigned& r2, unsigned& r3,
                                      uint32_t addr) {
    asm volatile("ldmatrix.sync.aligned.m8n8.x4.shared.b16 {%0,%1,%2,%3}, [%4];"
                 : "=r"(r0), "=r"(r1), "=r"(r2), "=r"(r3) : "r"(addr));
}
__device__ __forceinline__ void ldsm4t(unsigned& r0, unsigned& r1,
                                       unsigned& r2, unsigned& r3,
                                       uint32_t addr) {
    asm volatile("ldmatrix.sync.aligned.m8n8.x4.trans.shared.b16 {%0,%1,%2,%3}, [%4];"
                 : "=r"(r0), "=r"(r1), "=r"(r2), "=r"(r3) : "r"(addr));
}
__device__ __forceinline__ unsigned packh2(float a, float b) {
    __half2 h = __floats2half2_rn(a, b);
    return *(unsigned*)&h;
}
// Two fp16 exponentials (base 2) in one MUFU instruction.
__device__ __forceinline__ unsigned ex2h2(unsigned x) {
    unsigned r;
    asm("ex2.approx.f16x2 %0, %1;" : "=r"(r) : "r"(x));
    return r;
}
__device__ __forceinline__ float2 h2f2(unsigned x) {
    __half2 h = *(__half2*)&x;
    return __half22float2(h);
}

// ---------------------------------------------------------------------------
// Prepass: round x to fp16
// ---------------------------------------------------------------------------
__global__ __launch_bounds__(256) void round_kernel(
    const float* __restrict__ in, __half* __restrict__ outp)
{
    const int idx = blockIdx.x * 256 + threadIdx.x;
    float4 v = ((const float4*)in)[idx];
    __half2 h0 = __floats2half2_rn(v.x, v.y);
    __half2 h1 = __floats2half2_rn(v.z, v.w);
    uint2 o = { *(unsigned*)&h0, *(unsigned*)&h1 };
    ((uint2*)outp)[idx] = o;
}

// ---------------------------------------------------------------------------
// Weight transpose to fp16: Wt[n][k] = half(W[k][n])
// ---------------------------------------------------------------------------
__global__ __launch_bounds__(256) void transpose_kernel(
    const float* __restrict__ W, __half* __restrict__ Wt, int R, int Cc)
{
    __shared__ float t[32][33];
    const int bx = blockIdx.x * 32, by = blockIdx.y * 32;
    const int x = threadIdx.x & 31, y4 = (threadIdx.x >> 5) * 4;
    #pragma unroll
    for (int j = 0; j < 4; j++)
        t[y4 + j][x] = W[(long)(by + y4 + j) * Cc + bx + x];
    __syncthreads();
    #pragma unroll
    for (int j = 0; j < 4; j++)
        Wt[(long)(bx + y4 + j) * R + by + x] = __float2half_rn(t[x][y4 + j]);
}

// ---------------------------------------------------------------------------
// fp16 mma.sync GEMM + bias (R11 config): C = A @ Bt^T + bias
// 128x128 CTA tile, BK=64, 256 threads, 2-stage cp.async, 2 CTAs/SM.
// ---------------------------------------------------------------------------
#define HS 72
#define HTILE (128 * HS)   // halves per operand tile

template <bool HALF_OUT>
__global__ __launch_bounds__(256, 2) void gemm_fp16(
    const __half* __restrict__ A, const __half* __restrict__ Bt,
    const float* __restrict__ bias, void* __restrict__ Cout,
    int M, int N, int K)
{
    extern __shared__ __half hsm[];
    const int tid = threadIdx.x;
    const int lane = tid & 31, wid = tid >> 5;
    const int g = lane >> 2, tq = lane & 3;
    const int wm = (wid & 3) * 32, wn = (wid >> 2) * 64;
    const int bm = blockIdx.y * 128, bn = blockIdx.x * 128;
    const int sr = tid >> 3, sc8 = (tid & 7) * 8;

    const uint32_t sbase = smem_u32(hsm);
    const uint32_t a_base0 = sbase +
        ((wm + (lane & 15)) * HS + (lane >> 4) * 8) * 2;
    const uint32_t b_base0 = sbase + HTILE * 2 +
        ((wn + (lane & 7) + (lane >> 4) * 8) * HS + ((lane >> 3) & 1) * 8) * 2;

    float acc[2][8][4];
    #pragma unroll
    for (int mt = 0; mt < 2; mt++)
        #pragma unroll
        for (int nt = 0; nt < 8; nt++)
            #pragma unroll
            for (int j = 0; j < 4; j++) acc[mt][nt][j] = 0.f;

    const int NK = K / 64;
    auto issue = [&](int kt, int b) {
        __half* As = hsm + b * 2 * HTILE;
        __half* Bs = As + HTILE;
        const int k0 = kt * 64;
        #pragma unroll
        for (int i = 0; i < 4; i++) {
            int r = sr + 32 * i;
            CP16(smem_u32(As + r * HS + sc8),
                 A + (long)(bm + r) * K + k0 + sc8);
            CP16(smem_u32(Bs + r * HS + sc8),
                 Bt + (long)(bn + r) * K + k0 + sc8);
        }
        CP_COMMIT();
    };

    issue(0, 0);
    for (int kt = 0; kt < NK; kt++) {
        const int buf = kt & 1;
        if (kt + 1 < NK) { issue(kt + 1, buf ^ 1); CP_WAIT(1); }
        else             { CP_WAIT(0); }
        __syncthreads();

        const uint32_t a_buf = a_base0 + buf * 2 * HTILE * 2;
        const uint32_t b_buf = b_base0 + buf * 2 * HTILE * 2;
        #pragma unroll
        for (int ks = 0; ks < 4; ks++) {
            unsigned af[2][4];
            ldsm4(af[0][0], af[0][1], af[0][2], af[0][3], a_buf + ks * 32);
            ldsm4(af[1][0], af[1][1], af[1][2], af[1][3],
                  a_buf + 16 * HS * 2 + ks * 32);
            #pragma unroll
            for (int p = 0; p < 4; p++) {
                unsigned b0, b1, c0, c1;
                ldsm4(b0, b1, c0, c1, b_buf + p * 16 * HS * 2 + ks * 32);
                mma16(acc[0][2 * p],     af[0], b0, b1);
                mma16(acc[1][2 * p],     af[1], b0, b1);
                mma16(acc[0][2 * p + 1], af[0], c0, c1);
                mma16(acc[1][2 * p + 1], af[1], c0, c1);
            }
        }
        __syncthreads();
    }

    #pragma unroll
    for (int mt = 0; mt < 2; mt++) {
        const long r0 = bm + wm + mt * 16 + g;
        #pragma unroll
        for (int nt = 0; nt < 8; nt++) {
            const int col = bn + wn + nt * 8 + 2 * tq;
            const float bz0 = bias[col], bz1 = bias[col + 1];
            if (HALF_OUT) {
                __half* C = (__half*)Cout;
                __half2 v0 = __floats2half2_rn(acc[mt][nt][0] + bz0,
                                               acc[mt][nt][1] + bz1);
                __half2 v1 = __floats2half2_rn(acc[mt][nt][2] + bz0,
                                               acc[mt][nt][3] + bz1);
                *(__half2*)(C + r0 * N + col)       = v0;
                *(__half2*)(C + (r0 + 8) * N + col) = v1;
            } else {
                float* C = (float*)Cout;
                float2 v0 = { acc[mt][nt][0] + bz0, acc[mt][nt][1] + bz1 };
                float2 v1 = { acc[mt][nt][2] + bz0, acc[mt][nt][3] + bz1 };
                *(float2*)(C + r0 * N + col)       = v0;
                *(float2*)(C + (r0 + 8) * N + col) = v1;
            }
        }
    }
}

// ---------------------------------------------------------------------------
// Flash attention fp16 (R11 config + f16x2 exp):
// Br=128, Bc=64, 128 threads (4 warps), 3 CTAs/SM, 2-stage KV double buffer,
// P in registers. Softmax: d = s - m in f32, packed to half2, then ONE
// ex2.approx.f16x2 per pair writes the PV A-fragment directly; row sums
// rebuilt in f32 from the half2 results; l kept as per-thread partial.
// Smem (halves, stride 72): Q 128 | K 2x64 | V 2x64 = 55296 B.
// ---------------------------------------------------------------------------
#define QS_OFF 0
#define KS_OFF (128 * HS)
#define VS_OFF (128 * HS + 2 * 64 * HS)
#define KVBUF (64 * HS)                          // halves per K or V buffer
#define FL_HALVES (128 * HS + 4 * 64 * HS)       // 27648 halves = 55296 B
#define NTILES (SEQ / 64)                        // 32

__global__ __launch_bounds__(128, 3) void flash_fp16()
{
    extern __shared__ __half fsm[];
    __half* Qs = fsm + QS_OFF;

    const int tid = threadIdx.x;
    const int lane = tid & 31, w = tid >> 5;
    const int g = lane >> 2, tq = lane & 3;
    const int b = blockIdx.y / NHEADS, h = blockIdx.y % NHEADS;
    const int q0 = blockIdx.x * 128;
    const long rowbase = (long)b * SEQ;
    const float kscale = 0.125f * 1.44269504089f;   // 1/sqrt(d) * log2(e)

    const uint32_t q_base = smem_u32(Qs) +
        ((w * 32 + (lane & 15)) * HS + (lane >> 4) * 8) * 2;
    const uint32_t k_base = smem_u32(fsm + KS_OFF) +
        (((lane & 7) + (lane >> 4) * 8) * HS + ((lane >> 3) & 1) * 8) * 2;
    const uint32_t v_base = smem_u32(fsm + VS_OFF) +
        (((lane & 7) + ((lane >> 3) & 1) * 8) * HS + (lane >> 4) * 8) * 2;

    // Stage Q: 128 rows x 8 chunks of 8 halves (uint4), scale via f32.
    #pragma unroll
    for (int i = 0; i < 8; i++) {
        int idx = tid + 128 * i;
        int r = idx >> 3, c8 = (idx & 7) * 8;
        uint4 v = *(const uint4*)&g_qkv[(rowbase + q0 + r) * C3 + h * HD + c8];
        __half2* hp = (__half2*)&v;
        #pragma unroll
        for (int j = 0; j < 4; j++) {
            float2 f = __half22float2(hp[j]);
            hp[j] = __floats2half2_rn(f.x * kscale, f.y * kscale);
        }
        *(uint4*)(Qs + r * HS + c8) = v;
    }

    // KV staging: tile t into buffer bf
    auto issue_kv = [&](int t, int bf) {
        __half* Kd = fsm + KS_OFF + bf * KVBUF;
        __half* Vd = fsm + VS_OFF + bf * KVBUF;
        const int k0 = t * 64;
        #pragma unroll
        for (int i = 0; i < 4; i++) {
            int idx = tid + 128 * i;
            int r = idx >> 3, c8 = (idx & 7) * 8;
            long gb = (rowbase + k0 + r) * C3 + h * HD + c8;
            CP16(smem_u32(Kd + r * HS + c8), &g_qkv[gb + CH]);
            CP16(smem_u32(Vd + r * HS + c8), &g_qkv[gb + 2 * CH]);
        }
        CP_COMMIT();
    };

    float o[2][8][4];
    float m_i[2][2], l_p[2][2];   // l_p: per-thread PARTIAL row sums
    #pragma unroll
    for (int mt = 0; mt < 2; mt++) {
        m_i[mt][0] = m_i[mt][1] = -1e30f;
        l_p[mt][0] = l_p[mt][1] = 0.f;
        #pragma unroll
        for (int nt = 0; nt < 8; nt++)
            #pragma unroll
            for (int j = 0; j < 4; j++) o[mt][nt][j] = 0.f;
    }

    issue_kv(0, 0);
    for (int t = 0; t < NTILES; t++) {
        const int buf = t & 1;
        CP_WAIT(0);            // KV(t) landed
        __syncthreads();       // all warps done reading buf^1 (tile t-1)
        if (t + 1 < NTILES) issue_kv(t + 1, buf ^ 1);   // overlaps compute(t)

        const uint32_t k_buf = k_base + buf * KVBUF * 2;
        const uint32_t v_buf = v_base + buf * KVBUF * 2;

        // S = Q @ K^T  (4 x k16 over d=64)
        float s[2][8][4];
        #pragma unroll
        for (int mt = 0; mt < 2; mt++)
            #pragma unroll
            for (int nt = 0; nt < 8; nt++)
                #pragma unroll
                for (int j = 0; j < 4; j++) s[mt][nt][j] = 0.f;
        #pragma unroll
        for (int ks = 0; ks < 4; ks++) {
            unsigned af[2][4];
            ldsm4(af[0][0], af[0][1], af[0][2], af[0][3], q_base + ks * 32);
            ldsm4(af[1][0], af[1][1], af[1][2], af[1][3],
                  q_base + 16 * HS * 2 + ks * 32);
            #pragma unroll
            for (int p = 0; p < 4; p++) {
                unsigned b0, b1, c0, c1;
                ldsm4(b0, b1, c0, c1, k_buf + p * 16 * HS * 2 + ks * 32);
                mma16(s[0][2 * p],     af[0], b0, b1);
                mma16(s[1][2 * p],     af[1], b0, b1);
                mma16(s[0][2 * p + 1], af[0], c0, c1);
                mma16(s[1][2 * p + 1], af[1], c0, c1);
            }
        }

        // Online softmax (base-2): d = s - m in f32, pack half2, ex2.f16x2
        // produces the PV A-fragment; rs rebuilt in f32 from half2 results.
        unsigned pa[2][4][4];   // [mt][k16-step][frag]
        #pragma unroll
        for (int mt = 0; mt < 2; mt++) {
            float mx0 = -1e30f, mx1 = -1e30f;
            #pragma unroll
            for (int nt = 0; nt < 8; nt++) {
                mx0 = fmaxf(mx0, fmaxf(s[mt][nt][0], s[mt][nt][1]));
                mx1 = fmaxf(mx1, fmaxf(s[mt][nt][2], s[mt][nt][3]));
            }
            mx0 = fmaxf(mx0, __shfl_xor_sync(0xffffffffu, mx0, 1));
            mx0 = fmaxf(mx0, __shfl_xor_sync(0xffffffffu, mx0, 2));
            mx1 = fmaxf(mx1, __shfl_xor_sync(0xffffffffu, mx1, 1));
            mx1 = fmaxf(mx1, __shfl_xor_sync(0xffffffffu, mx1, 2));
            const float mn0 = fmaxf(m_i[mt][0], mx0), mn1 = fmaxf(m_i[mt][1], mx1);
            const float cr0 = exp2f(m_i[mt][0] - mn0), cr1 = exp2f(m_i[mt][1] - mn1);
            float rs0 = 0.f, rs1 = 0.f;
            #pragma unroll
            for (int j = 0; j < 4; j++) {      // k16 step = nt pair (2j, 2j+1)
                unsigned e0 = ex2h2(packh2(s[mt][2*j][0]   - mn0,
                                           s[mt][2*j][1]   - mn0));
                unsigned e1 = ex2h2(packh2(s[mt][2*j][2]   - mn1,
                                           s[mt][2*j][3]   - mn1));
                unsigned e2 = ex2h2(packh2(s[mt][2*j+1][0] - mn0,
                                           s[mt][2*j+1][1] - mn0));
                unsigned e3 = ex2h2(packh2(s[mt][2*j+1][2] - mn1,
                                           s[mt][2*j+1][3] - mn1));
                pa[mt][j][0] = e0; pa[mt][j][1] = e1;
                pa[mt][j][2] = e2; pa[mt][j][3] = e3;
                float2 f0 = h2f2(e0), f1 = h2f2(e1);
                float2 f2 = h2f2(e2), f3 = h2f2(e3);
                rs0 += (f0.x + f0.y) + (f2.x + f2.y);
                rs1 += (f1.x + f1.y) + (f3.x + f3.y);
            }
            l_p[mt][0] = l_p[mt][0] * cr0 + rs0;   // partial (quad-unreduced)
            l_p[mt][1] = l_p[mt][1] * cr1 + rs1;
            m_i[mt][0] = mn0; m_i[mt][1] = mn1;
            #pragma unroll
            for (int nt = 0; nt < 8; nt++) {
                o[mt][nt][0] *= cr0; o[mt][nt][1] *= cr0;
                o[mt][nt][2] *= cr1; o[mt][nt][3] *= cr1;
            }
        }

        // O += P @ V  (P from registers; V via ldmatrix.trans)
        #pragma unroll
        for (int ks = 0; ks < 4; ks++) {
            #pragma unroll
            for (int p = 0; p < 4; p++) {
                unsigned b0, b1, c0, c1;
                ldsm4t(b0, b1, c0, c1,
                       v_buf + ks * 16 * HS * 2 + p * 16 * 2);
                mma16(o[0][2 * p],     pa[0][ks], b0, b1);
                mma16(o[1][2 * p],     pa[1][ks], b0, b1);
                mma16(o[0][2 * p + 1], pa[0][ks], c0, c1);
                mma16(o[1][2 * p + 1], pa[1][ks], c0, c1);
            }
        }
    }

    // Epilogue: quad-reduce l partials, normalize, store fp16.
    #pragma unroll
    for (int mt = 0; mt < 2; mt++) {
        float l0 = l_p[mt][0], l1 = l_p[mt][1];
        l0 += __shfl_xor_sync(0xffffffffu, l0, 1);
        l0 += __shfl_xor_sync(0xffffffffu, l0, 2);
        l1 += __shfl_xor_sync(0xffffffffu, l1, 1);
        l1 += __shfl_xor_sync(0xffffffffu, l1, 2);
        const float inv0 = 1.f / l0, inv1 = 1.f / l1;
        const long r0 = rowbase + q0 + w * 32 + mt * 16 + g;
        #pragma unroll
        for (int nt = 0; nt < 8; nt++) {
            const int col = h * HD + nt * 8 + 2 * tq;
            *(__half2*)(g_att + r0 * CH + col) =
                __floats2half2_rn(o[mt][nt][0] * inv0, o[mt][nt][1] * inv0);
            *(__half2*)(g_att + (r0 + 8) * CH + col) =
                __floats2half2_rn(o[mt][nt][2] * inv1, o[mt][nt][3] * inv1);
        }
    }
}

// ---------------------------------------------------------------------------
extern "C" void kernel_launch(void* const* d_in, const int* in_sizes, int n_in,
                              void* d_out, int out_size)
{
    const float* x     = (const float*)d_in[0];
    const float* Wqkv  = (const float*)d_in[1];
    const float* bqkv  = (const float*)d_in[2];
    const float* Wproj = (const float*)d_in[3];
    const float* bproj = (const float*)d_in[4];
    float* out = (float*)d_out;

    __half *xr, *qkv_ptr, *att_ptr, *wqkvT, *wprojT;
    cudaGetSymbolAddress((void**)&xr, g_x);
    cudaGetSymbolAddress((void**)&qkv_ptr, g_qkv);
    cudaGetSymbolAddress((void**)&att_ptr, g_att);
    cudaGetSymbolAddress((void**)&wqkvT, g_wqkvT);
    cudaGetSymbolAddress((void**)&wprojT, g_wprojT);

    static int smem_set = 0;
    const int gemm_smem  = 4 * HTILE * sizeof(__half);    // 73728 B
    const int flash_smem = FL_HALVES * sizeof(__half);    // 55296 B
    if (!smem_set) {
        cudaFuncSetAttribute(gemm_fp16<true>,
            cudaFuncAttributeMaxDynamicSharedMemorySize, gemm_smem);
        cudaFuncSetAttribute(gemm_fp16<false>,
            cudaFuncAttributeMaxDynamicSharedMemorySize, gemm_smem);
        cudaFuncSetAttribute(flash_fp16,
            cudaFuncAttributeMaxDynamicSharedMemorySize, flash_smem);
        smem_set = 1;
    }

    // Pre-round x to fp16; transpose weights to fp16
    round_kernel<<<(MTOT * CH) / 1024, 256>>>(x, xr);
    transpose_kernel<<<dim3(C3 / 32, CH / 32), 256>>>(Wqkv, wqkvT, CH, C3);
    transpose_kernel<<<dim3(CH / 32, CH / 32), 256>>>(Wproj, wprojT, CH, CH);

    // QKV projection (fp16 output)
    gemm_fp16<true><<<dim3(C3 / 128, MTOT / 128), 256, gemm_smem>>>(
        xr, wqkvT, bqkv, qkv_ptr, MTOT, C3, CH);
    // Flash attention (3 CTAs/SM, double-buffered KV, P in regs, f16x2 exp)
    flash_fp16<<<dim3(SEQ / 128, BATCH * NHEADS), 128, flash_smem>>>();
    // Output projection (fp32 output)
    gemm_fp16<false><<<dim3(CH / 128, MTOT / 128), 256, gemm_smem>>>(
        att_ptr, wprojT, bproj, out, MTOT, CH, CH);
}